// round 5
// baseline (speedup 1.0000x reference)
#include <cuda_runtime.h>
#include <cstdint>

// EdgeFeature: B=4, D=64, N=4096, K=16
// out = [ edge_feature (4,128,4096,16) fp32 ; idx (4,65536) as fp32 ]

#define B_ 4
#define D_ 64
#define N_ 4096
#define K_ 16

// Scratch (static __device__ — no allocations allowed in kernel_launch)
__device__ float g_sq[B_ * N_];                       // 64 KB
__device__ float g_dist[(size_t)B_ * N_ * N_];        // 256 MB (fp32 dist, post-sqrt)
__device__ int   g_idx[B_ * N_ * K_];                 // 1 MB

// ---------------------------------------------------------------------------
// 1) squared norms (sequential ascending d, fmaf — matches the GEMM's dot
//    accumulation order so self-distance cancels to exactly 0.0f)
// ---------------------------------------------------------------------------
__global__ void sq_kernel(const float* __restrict__ pc) {
    int gid = blockIdx.x * blockDim.x + threadIdx.x;
    int b = gid >> 12;
    int n = gid & (N_ - 1);
    const float* X = pc + (size_t)b * D_ * N_;
    float acc = 0.0f;
    #pragma unroll
    for (int d = 0; d < D_; d++) {
        float v = X[d * N_ + n];
        acc = fmaf(v, v, acc);
    }
    g_sq[gid] = acc;
}

// ---------------------------------------------------------------------------
// 2) dist[b][i][j] = sqrt(max(sq_i + sq_j - 2*dot(x_i, x_j), 0))
//    Proven version: full grid, 128x128 CTA tile, 256 threads, 8x8 micro-tile,
//    scalar FFMA, coalesced float4 stores. (Unchanged from Round 2.)
// ---------------------------------------------------------------------------
__global__ __launch_bounds__(256, 2) void d2_kernel(const float* __restrict__ pc) {
    __shared__ float As[32][128];
    __shared__ float Bs[32][128];
    __shared__ float sqa[128];
    __shared__ float sqb[128];

    int b  = blockIdx.z;
    int i0 = blockIdx.y * 128;
    int j0 = blockIdx.x * 128;
    const float* X = pc + (size_t)b * D_ * N_;
    int t = threadIdx.x;

    if (t < 128) sqa[t]       = g_sq[b * N_ + i0 + t];
    else         sqb[t - 128] = g_sq[b * N_ + j0 + (t - 128)];

    int r = t >> 4;
    int c = t & 15;

    float acc[8][8];
    #pragma unroll
    for (int ii = 0; ii < 8; ii++)
        #pragma unroll
        for (int jj = 0; jj < 8; jj++)
            acc[ii][jj] = 0.0f;

    for (int dc = 0; dc < D_; dc += 32) {
        __syncthreads();
        for (int l = t; l < 1024; l += 256) {
            int d  = l >> 5;
            int i4 = (l & 31) << 2;
            *(float4*)&As[d][i4] = *(const float4*)&X[(size_t)(dc + d) * N_ + i0 + i4];
            *(float4*)&Bs[d][i4] = *(const float4*)&X[(size_t)(dc + d) * N_ + j0 + i4];
        }
        __syncthreads();

        #pragma unroll 8
        for (int d = 0; d < 32; d++) {
            float a[8], bb[8];
            *(float4*)&a[0]  = *(float4*)&As[d][r * 8];
            *(float4*)&a[4]  = *(float4*)&As[d][r * 8 + 4];
            *(float4*)&bb[0] = *(float4*)&Bs[d][c * 8];
            *(float4*)&bb[4] = *(float4*)&Bs[d][c * 8 + 4];
            #pragma unroll
            for (int ii = 0; ii < 8; ii++)
                #pragma unroll
                for (int jj = 0; jj < 8; jj++)
                    acc[ii][jj] = fmaf(a[ii], bb[jj], acc[ii][jj]);
        }
    }

    #pragma unroll
    for (int ii = 0; ii < 8; ii++) {
        int   row = i0 + r * 8 + ii;
        float si  = sqa[r * 8 + ii];
        float* dst = g_dist + ((size_t)(b * N_ + row) << 12) + j0 + c * 8;
        float v[8];
        #pragma unroll
        for (int jj = 0; jj < 8; jj++) {
            float s = si + sqb[c * 8 + jj];
            v[jj] = sqrtf(fmaxf(s - 2.0f * acc[ii][jj], 0.0f));
        }
        *(float4*)&dst[0] = *(float4*)&v[0];
        *(float4*)&dst[4] = *(float4*)&v[4];
    }
}

// ---------------------------------------------------------------------------
// 3) per-row top-(K+1): TWO-LEVEL histogram (exponent coarse, 11 mantissa
//    bits fine) + exact warp argmin on the tiny candidate set.
//    dist values concentrate in ONE exponent, so the fine level resolves
//    2048 buckets WITHIN that exponent (~2 values/bucket). All histogram
//    atomics are warp-aggregated (__match_any / ballot) to avoid ATOMS
//    serialization. Final order = u64 key (bits<<32)|j == lax.top_k order.
// ---------------------------------------------------------------------------
__global__ __launch_bounds__(256) void select_kernel(float* __restrict__ out_idx_f) {
    __shared__ int hist[2048];
    __shared__ unsigned long long buf[4096];
    __shared__ int wsum[8];
    __shared__ int Esh, below_sh, Fsh, cnt;

    int row = blockIdx.x;                      // b*4096 + i
    const float* src = g_dist + (size_t)row * N_;
    int t = threadIdx.x;
    int lane = t & 31, w = t >> 5;
    unsigned lmask_lt = (1u << lane) - 1u;

    #pragma unroll
    for (int q = 0; q < 8; q++) hist[t + 256 * q] = 0;
    if (t == 0) cnt = 0;
    __syncthreads();

    unsigned bits[16];
    #pragma unroll
    for (int jj = 0; jj < 4; jj++) {
        float4 v = *(const float4*)&src[(t + jj * 256) * 4];
        bits[jj * 4 + 0] = __float_as_uint(v.x);
        bits[jj * 4 + 1] = __float_as_uint(v.y);
        bits[jj * 4 + 2] = __float_as_uint(v.z);
        bits[jj * 4 + 3] = __float_as_uint(v.w);
    }
    // NOTE: value at linear position t*? -> recompute j later from layout:
    // element jj of this thread is column (t + jj_outer*256)*4 + jj_inner,
    // i.e. j = t*4? No: float4 at (t + q*256)*4 covers cols 4t+1024q .. +3.

    // coarse histogram: exponent (bits>>23), warp-aggregated
    #pragma unroll
    for (int jj = 0; jj < 16; jj++) {
        int e = bits[jj] >> 23;
        unsigned m = __match_any_sync(0xffffffffu, e);
        if ((m & lmask_lt) == 0)               // leader
            atomicAdd(&hist[e], __popc(m));
    }
    __syncthreads();

    // coarse scan: warp 0 owns all 256 exponent buckets (8 per lane)
    if (w == 0) {
        int h[8], s = 0;
        #pragma unroll
        for (int q = 0; q < 8; q++) { h[q] = hist[lane * 8 + q]; s += h[q]; }
        int x = s;
        #pragma unroll
        for (int off = 1; off < 32; off <<= 1) {
            int y = __shfl_up_sync(0xffffffffu, x, off);
            if (lane >= off) x += y;
        }
        int cum = x - s;                       // exclusive prefix
        #pragma unroll
        for (int q = 0; q < 8; q++) {
            if (cum < (K_ + 1) && cum + h[q] >= (K_ + 1)) {
                Esh = lane * 8 + q;
                below_sh = cum;
            }
            cum += h[q];
        }
    }
    __syncthreads();
    int E = Esh, need = (K_ + 1) - below_sh;

    // re-zero hist for fine level
    #pragma unroll
    for (int q = 0; q < 8; q++) hist[t + 256 * q] = 0;
    __syncthreads();

    // fine histogram: 11 mantissa bits within exponent E, warp-aggregated
    #pragma unroll
    for (int jj = 0; jj < 16; jj++) {
        int f = ((int)(bits[jj] >> 23) == E) ? (int)((bits[jj] >> 12) & 2047) : -1;
        unsigned m = __match_any_sync(0xffffffffu, f);
        if (f >= 0 && (m & lmask_lt) == 0)
            atomicAdd(&hist[f], __popc(m));
    }
    __syncthreads();

    // fine scan over 2048 buckets (256 threads x 8), threshold = need
    {
        int h[8], s = 0;
        #pragma unroll
        for (int q = 0; q < 8; q++) { h[q] = hist[t * 8 + q]; s += h[q]; }
        int x = s;
        #pragma unroll
        for (int off = 1; off < 32; off <<= 1) {
            int y = __shfl_up_sync(0xffffffffu, x, off);
            if (lane >= off) x += y;
        }
        if (lane == 31) wsum[w] = x;
        __syncthreads();
        int wo = 0;
        #pragma unroll
        for (int q = 0; q < 8; q++) wo += (q < w) ? wsum[q] : 0;
        int cum = wo + x - s;
        #pragma unroll
        for (int q = 0; q < 8; q++) {
            if (cum < need && cum + h[q] >= need) Fsh = t * 8 + q;
            cum += h[q];
        }
    }
    __syncthreads();
    int F = Fsh;

    // compaction: exp<E, or exp==E && fine<=F  (ballot-aggregated append)
    #pragma unroll
    for (int jj = 0; jj < 16; jj++) {
        int e = bits[jj] >> 23;
        int f = (bits[jj] >> 12) & 2047;
        bool take = (e < E) || (e == E && f <= F);
        unsigned m = __ballot_sync(0xffffffffu, take);
        int base = 0;
        if (lane == __ffs(m) - 1 && m) base = atomicAdd(&cnt, __popc(m));
        if (m) base = __shfl_sync(0xffffffffu, base, __ffs(m) - 1);
        if (take) {
            // column index of bits[jj]: float4 layout above
            int j = (t + (jj >> 2) * 256) * 4 + (jj & 3);
            buf[base + __popc(m & lmask_lt)] =
                ((unsigned long long)bits[jj] << 32) | (unsigned)j;
        }
    }
    __syncthreads();

    // exact top-17 on the tiny candidate set (warp 0)
    if (w == 0) {
        int n = cnt;
        for (int p = 0; p <= K_; p++) {
            unsigned long long m = 0xFFFFFFFFFFFFFFFFull;
            for (int i = lane; i < n; i += 32) m = (buf[i] < m) ? buf[i] : m;
            #pragma unroll
            for (int off = 16; off; off >>= 1) {
                unsigned long long o = __shfl_xor_sync(0xffffffffu, m, off);
                m = (o < m) ? o : m;
            }
            for (int i = lane; i < n; i += 32)
                if (buf[i] == m) buf[i] = 0xFFFFFFFFFFFFFFFFull;
            if (lane == 0 && p > 0) {
                int j = (int)(m & 0xFFFFFFFFu);
                g_idx[row * K_ + (p - 1)]     = j;
                out_idx_f[row * K_ + (p - 1)] = (float)j;
            }
        }
    }
}

// ---------------------------------------------------------------------------
// 4) gather v3: smem-row gather. Block = (b, channel c, n-octant).
//    The whole channel row pc[b][c][:] (16 KB) sits in smem, so all scattered
//    reads are LDS; every gmem access (idx, stores) is coalesced.
// ---------------------------------------------------------------------------
__global__ __launch_bounds__(256) void gather_kernel(const float* __restrict__ pc,
                                                     float* __restrict__ out) {
    __shared__ float rowv[N_];

    int blk = blockIdx.x;            // 2048 blocks: b(2) | c(6) | s(3)
    int s   = blk & 7;
    int c   = (blk >> 3) & 63;
    int b   = blk >> 9;
    int t   = threadIdx.x;
    const float* src = pc + ((size_t)b * D_ + c) * N_;

    #pragma unroll
    for (int q = 0; q < 4; q++)
        ((float4*)rowv)[t + q * 256] = ((const float4*)src)[t + q * 256];
    __syncthreads();

    int n0 = s * 512;
    const int* idxp = g_idx + ((size_t)b * N_ + n0) * K_;
    size_t obase = (size_t)b * 2 * D_ * N_ * K_ + ((size_t)c * N_ + n0) * K_;
    float* oc = out + obase;                       // central channel c
    float* on = out + obase + (size_t)D_ * N_ * K_; // neighbor-central c+64

    #pragma unroll 4
    for (int it = 0; it < 32; it++) {
        int l = t + it * 256;            // 8192 (n,k) pairs in this octant
        int n = l >> 4;
        int j = idxp[l];                 // coalesced
        float ce = rowv[n0 + n];
        float nb = rowv[j];              // LDS gather
        oc[l] = ce;
        on[l] = nb - ce;
    }
}

// ---------------------------------------------------------------------------
extern "C" void kernel_launch(void* const* d_in, const int* in_sizes, int n_in,
                              void* d_out, int out_size) {
    const float* pc = (const float*)d_in[0];
    float* out = (float*)d_out;
    float* out_idx = out + (size_t)B_ * 2 * D_ * N_ * K_;

    sq_kernel<<<(B_ * N_) / 256, 256>>>(pc);
    dim3 gg(N_ / 128, N_ / 128, B_);
    d2_kernel<<<gg, 256>>>(pc);
    select_kernel<<<B_ * N_, 256>>>(out_idx);
    gather_kernel<<<B_ * D_ * 8, 256>>>(pc, out);
}

// round 6
// speedup vs baseline: 1.8070x; 1.8070x over previous
#include <cuda_runtime.h>
#include <cstdint>

// EdgeFeature: B=4, D=64, N=4096, K=16
// out = [ edge_feature (4,128,4096,16) fp32 ; idx (4,65536) as fp32 ]

#define B_ 4
#define D_ 64
#define N_ 4096
#define K_ 16

// Scratch (static __device__ — no allocations allowed in kernel_launch)
__device__ float g_sq[B_ * N_];                       // 64 KB
__device__ float g_dist[(size_t)B_ * N_ * N_];        // 256 MB (fp32 dist, post-sqrt)
__device__ int   g_idx[B_ * N_ * K_];                 // 1 MB

// ---------------------------------------------------------------------------
// 1) squared norms (sequential ascending d, fmaf — matches the GEMM's dot
//    accumulation order so self-distance cancels to exactly 0.0f)
// ---------------------------------------------------------------------------
__global__ void sq_kernel(const float* __restrict__ pc) {
    int gid = blockIdx.x * blockDim.x + threadIdx.x;
    int b = gid >> 12;
    int n = gid & (N_ - 1);
    const float* X = pc + (size_t)b * D_ * N_;
    float acc = 0.0f;
    #pragma unroll
    for (int d = 0; d < D_; d++) {
        float v = X[d * N_ + n];
        acc = fmaf(v, v, acc);
    }
    g_sq[gid] = acc;
}

// ---------------------------------------------------------------------------
// 2) dist[b][i][j] = sqrt(max(sq_i + sq_j - 2*dot(x_i, x_j), 0))
//    Proven Round-2 version: full grid, 128x128 CTA tile, 256 threads,
//    8x8 micro-tile, scalar FFMA, coalesced float4 stores. UNCHANGED.
// ---------------------------------------------------------------------------
__global__ __launch_bounds__(256, 2) void d2_kernel(const float* __restrict__ pc) {
    __shared__ float As[32][128];
    __shared__ float Bs[32][128];
    __shared__ float sqa[128];
    __shared__ float sqb[128];

    int b  = blockIdx.z;
    int i0 = blockIdx.y * 128;
    int j0 = blockIdx.x * 128;
    const float* X = pc + (size_t)b * D_ * N_;
    int t = threadIdx.x;

    if (t < 128) sqa[t]       = g_sq[b * N_ + i0 + t];
    else         sqb[t - 128] = g_sq[b * N_ + j0 + (t - 128)];

    int r = t >> 4;
    int c = t & 15;

    float acc[8][8];
    #pragma unroll
    for (int ii = 0; ii < 8; ii++)
        #pragma unroll
        for (int jj = 0; jj < 8; jj++)
            acc[ii][jj] = 0.0f;

    for (int dc = 0; dc < D_; dc += 32) {
        __syncthreads();
        for (int l = t; l < 1024; l += 256) {
            int d  = l >> 5;
            int i4 = (l & 31) << 2;
            *(float4*)&As[d][i4] = *(const float4*)&X[(size_t)(dc + d) * N_ + i0 + i4];
            *(float4*)&Bs[d][i4] = *(const float4*)&X[(size_t)(dc + d) * N_ + j0 + i4];
        }
        __syncthreads();

        #pragma unroll 8
        for (int d = 0; d < 32; d++) {
            float a[8], bb[8];
            *(float4*)&a[0]  = *(float4*)&As[d][r * 8];
            *(float4*)&a[4]  = *(float4*)&As[d][r * 8 + 4];
            *(float4*)&bb[0] = *(float4*)&Bs[d][c * 8];
            *(float4*)&bb[4] = *(float4*)&Bs[d][c * 8 + 4];
            #pragma unroll
            for (int ii = 0; ii < 8; ii++)
                #pragma unroll
                for (int jj = 0; jj < 8; jj++)
                    acc[ii][jj] = fmaf(a[ii], bb[jj], acc[ii][jj]);
        }
    }

    #pragma unroll
    for (int ii = 0; ii < 8; ii++) {
        int   row = i0 + r * 8 + ii;
        float si  = sqa[r * 8 + ii];
        float* dst = g_dist + ((size_t)(b * N_ + row) << 12) + j0 + c * 8;
        float v[8];
        #pragma unroll
        for (int jj = 0; jj < 8; jj++) {
            float s = si + sqb[c * 8 + jj];
            v[jj] = sqrtf(fmaxf(s - 2.0f * acc[ii][jj], 0.0f));
        }
        *(float4*)&dst[0] = *(float4*)&v[0];
        *(float4*)&dst[4] = *(float4*)&v[4];
    }
}

// ---------------------------------------------------------------------------
// 3) select v3: threshold-filter, NO histograms, NO hot atomics.
//    tau_w = 17th smallest of the warp's 32 lane-minima (bitonic shfl sort)
//    -> >=17 values <= tau_w in that warp, and row-17th <= tau_w. Block tau =
//    min over warps. Filter val<=tau, compact with ONE atomic per warp, then
//    exact 17-pass warp argmin on u64 keys (bits<<32)|j == lax.top_k order.
//    Worst case (all values <= tau) still correct: buf holds 4096.
// ---------------------------------------------------------------------------
__global__ __launch_bounds__(256) void select_kernel(float* __restrict__ out_idx_f) {
    __shared__ unsigned long long buf[4096];
    __shared__ float wtau[8];
    __shared__ int cnt;

    int row = blockIdx.x;                      // b*4096 + i
    const float* src = g_dist + (size_t)row * N_;
    int t = threadIdx.x;
    int lane = t & 31, w = t >> 5;
    unsigned lmask_lt = (1u << lane) - 1u;

    if (t == 0) cnt = 0;

    // warp w owns cols [512w, 512w+512): lane reads 4 coalesced float4s
    float4 vv[4];
    #pragma unroll
    for (int u = 0; u < 4; u++)
        vv[u] = ((const float4*)src)[128 * w + lane + 32 * u];

    // lane min of its 16 values
    float mn;
    {
        float m0 = fminf(fminf(vv[0].x, vv[0].y), fminf(vv[0].z, vv[0].w));
        float m1 = fminf(fminf(vv[1].x, vv[1].y), fminf(vv[1].z, vv[1].w));
        float m2 = fminf(fminf(vv[2].x, vv[2].y), fminf(vv[2].z, vv[2].w));
        float m3 = fminf(fminf(vv[3].x, vv[3].y), fminf(vv[3].z, vv[3].w));
        mn = fminf(fminf(m0, m1), fminf(m2, m3));
    }

    // bitonic sort of lane minima across the warp (ascending by lane)
    float x = mn;
    #pragma unroll
    for (int k = 2; k <= 32; k <<= 1) {
        #pragma unroll
        for (int j2 = k >> 1; j2 > 0; j2 >>= 1) {
            float other = __shfl_xor_sync(0xffffffffu, x, j2);
            bool up    = ((lane & k) == 0);
            bool small = ((lane & j2) == 0);
            x = (small == up) ? fminf(x, other) : fmaxf(x, other);
        }
    }
    float tau_w = __shfl_sync(0xffffffffu, x, K_);   // 17th smallest lane-min
    if (lane == 0) wtau[w] = tau_w;
    __syncthreads();
    float tau = wtau[0];
    #pragma unroll
    for (int q = 1; q < 8; q++) tau = fminf(tau, wtau[q]);

    // filter + warp-aggregated compaction (one atomic per warp)
    float    val[16];
    unsigned msk[4 * 4];
    int tot = 0;
    #pragma unroll
    for (int u = 0; u < 4; u++) {
        val[u * 4 + 0] = vv[u].x; val[u * 4 + 1] = vv[u].y;
        val[u * 4 + 2] = vv[u].z; val[u * 4 + 3] = vv[u].w;
    }
    #pragma unroll
    for (int e = 0; e < 16; e++) {
        msk[e] = __ballot_sync(0xffffffffu, val[e] <= tau);
        tot += __popc(msk[e]);
    }
    int wbase = 0;
    if (lane == 0) wbase = atomicAdd(&cnt, tot);
    wbase = __shfl_sync(0xffffffffu, wbase, 0);
    int off = 0;
    #pragma unroll
    for (int e = 0; e < 16; e++) {
        if (val[e] <= tau) {
            int j = (128 * w + lane + 32 * (e >> 2)) * 4 + (e & 3);
            buf[wbase + off + __popc(msk[e] & lmask_lt)] =
                ((unsigned long long)__float_as_uint(val[e]) << 32) | (unsigned)j;
        }
        off += __popc(msk[e]);
    }
    __syncthreads();

    // exact top-17 on the candidate set (warp 0; n typically ~100-300)
    if (w == 0) {
        int n = cnt;
        for (int p = 0; p <= K_; p++) {
            unsigned long long m = 0xFFFFFFFFFFFFFFFFull;
            for (int i = lane; i < n; i += 32) m = (buf[i] < m) ? buf[i] : m;
            #pragma unroll
            for (int o2 = 16; o2; o2 >>= 1) {
                unsigned long long o = __shfl_xor_sync(0xffffffffu, m, o2);
                m = (o < m) ? o : m;
            }
            for (int i = lane; i < n; i += 32)
                if (buf[i] == m) buf[i] = 0xFFFFFFFFFFFFFFFFull;
            if (lane == 0 && p > 0) {
                int j = (int)(m & 0xFFFFFFFFu);
                g_idx[row * K_ + (p - 1)]     = j;
                out_idx_f[row * K_ + (p - 1)] = (float)j;
            }
        }
    }
}

// ---------------------------------------------------------------------------
// 4) gather v3 (proven 37us): smem-row gather. Block = (b, channel, octant).
// ---------------------------------------------------------------------------
__global__ __launch_bounds__(256) void gather_kernel(const float* __restrict__ pc,
                                                     float* __restrict__ out) {
    __shared__ float rowv[N_];

    int blk = blockIdx.x;            // 2048 blocks: b(2) | c(6) | s(3)
    int s   = blk & 7;
    int c   = (blk >> 3) & 63;
    int b   = blk >> 9;
    int t   = threadIdx.x;
    const float* src = pc + ((size_t)b * D_ + c) * N_;

    #pragma unroll
    for (int q = 0; q < 4; q++)
        ((float4*)rowv)[t + q * 256] = ((const float4*)src)[t + q * 256];
    __syncthreads();

    int n0 = s * 512;
    const int* idxp = g_idx + ((size_t)b * N_ + n0) * K_;
    size_t obase = (size_t)b * 2 * D_ * N_ * K_ + ((size_t)c * N_ + n0) * K_;
    float* oc = out + obase;                        // central channel c
    float* on = out + obase + (size_t)D_ * N_ * K_; // neighbor-central c+64

    #pragma unroll 4
    for (int it = 0; it < 32; it++) {
        int l = t + it * 256;
        int n = l >> 4;
        int j = idxp[l];
        float ce = rowv[n0 + n];
        float nb = rowv[j];
        oc[l] = ce;
        on[l] = nb - ce;
    }
}

// ---------------------------------------------------------------------------
extern "C" void kernel_launch(void* const* d_in, const int* in_sizes, int n_in,
                              void* d_out, int out_size) {
    const float* pc = (const float*)d_in[0];
    float* out = (float*)d_out;
    float* out_idx = out + (size_t)B_ * 2 * D_ * N_ * K_;

    sq_kernel<<<(B_ * N_) / 256, 256>>>(pc);
    dim3 gg(N_ / 128, N_ / 128, B_);
    d2_kernel<<<gg, 256>>>(pc);
    select_kernel<<<B_ * N_, 256>>>(out_idx);
    gather_kernel<<<B_ * D_ * 8, 256>>>(pc, out);
}